// round 1
// baseline (speedup 1.0000x reference)
#include <cuda_runtime.h>
#include <cstdint>

#define T_TOK 8192
#define DIM   1024
#define HID   2752
#define NE    8
#define TOPK  2

#define BM 128
#define BN 64
#define BK 32
#define SA (BM*(BK+4))        // 4608 floats
#define SB (BN*(BK+4))        // 2304 floats
#define ST1 (SA + 2*SB)       // ffn1 stage: 9216 floats
#define ST2 (SA + SB)         // ffn2 stage: 6912 floats
#define SMEM1 (2*ST1*4 + BM*4)  // 73728 + 512 = 74240 B
#define SMEM2 (2*ST2*4)          // 55296 B

// ---------------- device scratch (no runtime allocation allowed) -------------
__device__ int   g_counts[NE];
__device__ int   g_offsets[NE + 1];
__device__ int   g_fill[NE];
__device__ int   g_topk_idx[T_TOK * TOPK];
__device__ float g_topk_w[T_TOK * TOPK];
__device__ int   g_perm[T_TOK * TOPK];
__device__ float g_coef[T_TOK * TOPK];
// hidden activations for routed slots (T*K) + shared expert (T)
__device__ float g_h[(size_t)(T_TOK * TOPK + T_TOK) * HID];

// ---------------- small helpers ----------------------------------------------
__device__ __forceinline__ uint32_t f2tf(float f) {
    uint32_t r;
    asm("cvt.rna.tf32.f32 %0, %1;" : "=r"(r) : "f"(f));
    return r;
}
__device__ __forceinline__ uint32_t smem_u32(const void* p) {
    return (uint32_t)__cvta_generic_to_shared(p);
}
__device__ __forceinline__ void cp16(uint32_t dst, const void* src) {
    asm volatile("cp.async.cg.shared.global [%0], [%1], 16;\n" :: "r"(dst), "l"(src));
}
__device__ __forceinline__ void cp_commit() { asm volatile("cp.async.commit_group;\n"); }
template <int N>
__device__ __forceinline__ void cp_wait() { asm volatile("cp.async.wait_group %0;\n" :: "n"(N)); }

// mma.m16n8k8 tf32, D += A*B (C aliased to D)
__device__ __forceinline__ void mma_tf32(float* d, const uint32_t* a, const uint32_t* b) {
    asm volatile(
        "mma.sync.aligned.m16n8k8.row.col.f32.tf32.tf32.f32 "
        "{%0,%1,%2,%3},{%4,%5,%6,%7},{%8,%9},{%0,%1,%2,%3};\n"
        : "+f"(d[0]), "+f"(d[1]), "+f"(d[2]), "+f"(d[3])
        : "r"(a[0]), "r"(a[1]), "r"(a[2]), "r"(a[3]), "r"(b[0]), "r"(b[1]));
}

// ---------------- kernel 0: zero output + counters ---------------------------
__global__ void zero_kernel(float* __restrict__ out) {
    size_t n = (size_t)T_TOK * DIM;
    for (size_t i = (size_t)blockIdx.x * blockDim.x + threadIdx.x; i < n;
         i += (size_t)gridDim.x * blockDim.x)
        out[i] = 0.f;
    if (blockIdx.x == 0 && threadIdx.x < NE) g_counts[threadIdx.x] = 0;
}

// ---------------- kernel 1: gate (one warp per token) ------------------------
__global__ void gate_kernel(const float* __restrict__ x, const float* __restrict__ gw) {
    int warp = threadIdx.x >> 5, lane = threadIdx.x & 31;
    int t = blockIdx.x * 8 + warp;
    const float* xr = x + (size_t)t * DIM;
    float acc[NE];
#pragma unroll
    for (int e = 0; e < NE; e++) acc[e] = 0.f;
    for (int k = lane; k < DIM; k += 32) {
        float xv = xr[k];
#pragma unroll
        for (int e = 0; e < NE; e++) acc[e] += xv * gw[e * DIM + k];
    }
#pragma unroll
    for (int e = 0; e < NE; e++)
#pragma unroll
        for (int o = 16; o > 0; o >>= 1) acc[e] += __shfl_xor_sync(0xffffffffu, acc[e], o);
    if (lane == 0) {
        float mx = acc[0];
#pragma unroll
        for (int e = 1; e < NE; e++) mx = fmaxf(mx, acc[e]);
        float p[NE], s = 0.f;
#pragma unroll
        for (int e = 0; e < NE; e++) { p[e] = expf(acc[e] - mx); s += p[e]; }
        float inv = 1.f / s;
#pragma unroll
        for (int e = 0; e < NE; e++) p[e] *= inv;
        int i0 = 0; float b0 = p[0];
#pragma unroll
        for (int e = 1; e < NE; e++) if (p[e] > b0) { b0 = p[e]; i0 = e; }
        int i1 = -1; float b1 = -1.f;
#pragma unroll
        for (int e = 0; e < NE; e++) if (e != i0 && p[e] > b1) { b1 = p[e]; i1 = e; }
        float wn = 1.f / (b0 + b1 + 1e-20f);
        g_topk_idx[2 * t] = i0;     g_topk_idx[2 * t + 1] = i1;
        g_topk_w[2 * t] = b0 * wn;  g_topk_w[2 * t + 1] = b1 * wn;
        atomicAdd(&g_counts[i0], 1);
        atomicAdd(&g_counts[i1], 1);
    }
}

// ---------------- kernel 2: tiny scan ----------------------------------------
__global__ void scan_kernel() {
    if (threadIdx.x == 0) {
        int o = 0;
        for (int e = 0; e < NE; e++) { g_offsets[e] = o; o += g_counts[e]; g_fill[e] = 0; }
        g_offsets[NE] = o;
    }
}

// ---------------- kernel 3: scatter tokens into expert segments --------------
__global__ void scatter_kernel() {
    int t = blockIdx.x * blockDim.x + threadIdx.x;
    if (t >= T_TOK) return;
#pragma unroll
    for (int k = 0; k < TOPK; k++) {
        int e = g_topk_idx[2 * t + k];
        int pos = g_offsets[e] + atomicAdd(&g_fill[e], 1);
        g_perm[pos] = t;
        g_coef[pos] = g_topk_w[2 * t + k];
    }
}

// ---------------- kernel 4: FFN1 — h = silu(X W1^T) * (X W3^T) ---------------
// grid: (HID/BN=43, T/BM=64, 9 segments), block 256
__global__ __launch_bounds__(256) void ffn1_kernel(
    const float* __restrict__ x,
    const float* __restrict__ w1, const float* __restrict__ w3,
    const float* __restrict__ sw1, const float* __restrict__ sw3)
{
    extern __shared__ float smem[];
    const int z = blockIdx.z;
    const int rows = (z < NE) ? g_counts[z] : T_TOK;
    const int m0 = blockIdx.y * BM;
    if (m0 >= rows) return;
    const int segoff = (z < NE) ? g_offsets[z] : 0;
    const size_t hbase = (z < NE) ? (size_t)g_offsets[z] : (size_t)(T_TOK * TOPK);
    const float* W1 = (z < NE) ? (w1 + (size_t)z * HID * DIM) : sw1;
    const float* W3 = (z < NE) ? (w3 + (size_t)z * HID * DIM) : sw3;
    const int n0 = blockIdx.x * BN;

    const int tid = threadIdx.x;
    int* stok = (int*)(smem + 2 * ST1);
    if (tid < BM) {
        int r = m0 + tid;
        int rr = (r < rows) ? r : m0;      // clamp to a valid in-segment row
        stok[tid] = (z < NE) ? g_perm[segoff + rr] : rr;
    }
    __syncthreads();

    auto loadA = [&](int it, int buf) {
        float* As = smem + buf * ST1;
        int kt = it * BK;
#pragma unroll
        for (int i = 0; i < 4; i++) {
            int j = tid + i * 256;
            int r = j >> 3, kq = j & 7;
            const float* src = x + (size_t)stok[r] * DIM + kt + kq * 4;
            cp16(smem_u32(&As[r * (BK + 4) + kq * 4]), src);
        }
    };
    auto loadB = [&](int it, int buf) {
        float* B1 = smem + buf * ST1 + SA;
        float* B3 = B1 + SB;
        int kt = it * BK;
#pragma unroll
        for (int i = 0; i < 2; i++) {
            int j = tid + i * 256;
            int n = j >> 3, kq = j & 7;
            size_t go = (size_t)(n0 + n) * DIM + kt + kq * 4;
            cp16(smem_u32(&B1[n * (BK + 4) + kq * 4]), W1 + go);
            cp16(smem_u32(&B3[n * (BK + 4) + kq * 4]), W3 + go);
        }
    };

    const int lane = tid & 31, warp = tid >> 5;
    const int wm = warp & 3, wn = warp >> 2;   // 4x2 warp grid; warp tile 32x32
    const int g = lane >> 2, tg = lane & 3;

    float accG[2][4][4], accU[2][4][4];
#pragma unroll
    for (int a = 0; a < 2; a++)
#pragma unroll
        for (int b = 0; b < 4; b++)
#pragma unroll
            for (int c = 0; c < 4; c++) { accG[a][b][c] = 0.f; accU[a][b][c] = 0.f; }

    const int NIT = DIM / BK;  // 32
    loadA(0, 0); loadB(0, 0); cp_commit();
    for (int it = 0; it < NIT; ++it) {
        int buf = it & 1;
        if (it + 1 < NIT) { loadA(it + 1, buf ^ 1); loadB(it + 1, buf ^ 1); cp_commit(); cp_wait<1>(); }
        else               { cp_wait<0>(); }
        __syncthreads();
        float* As = smem + buf * ST1;
        float* B1 = As + SA;
        float* B3 = B1 + SB;
#pragma unroll
        for (int kk = 0; kk < 4; kk++) {
            int kb = kk * 8;
            uint32_t af[2][4];
#pragma unroll
            for (int mi = 0; mi < 2; mi++) {
                int mb = wm * 32 + mi * 16;
                af[mi][0] = f2tf(As[(mb + g    ) * (BK + 4) + kb + tg    ]);
                af[mi][1] = f2tf(As[(mb + g + 8) * (BK + 4) + kb + tg    ]);
                af[mi][2] = f2tf(As[(mb + g    ) * (BK + 4) + kb + tg + 4]);
                af[mi][3] = f2tf(As[(mb + g + 8) * (BK + 4) + kb + tg + 4]);
            }
#pragma unroll
            for (int ni = 0; ni < 4; ni++) {
                int nb = wn * 32 + ni * 8;
                uint32_t bf1[2], bf3[2];
                bf1[0] = f2tf(B1[(nb + g) * (BK + 4) + kb + tg    ]);
                bf1[1] = f2tf(B1[(nb + g) * (BK + 4) + kb + tg + 4]);
                bf3[0] = f2tf(B3[(nb + g) * (BK + 4) + kb + tg    ]);
                bf3[1] = f2tf(B3[(nb + g) * (BK + 4) + kb + tg + 4]);
#pragma unroll
                for (int mi = 0; mi < 2; mi++) {
                    mma_tf32(accG[mi][ni], af[mi], bf1);
                    mma_tf32(accU[mi][ni], af[mi], bf3);
                }
            }
        }
        __syncthreads();
    }

    // epilogue: silu(g)*u -> scratch
#pragma unroll
    for (int mi = 0; mi < 2; mi++) {
#pragma unroll
        for (int ni = 0; ni < 4; ni++) {
            int rbase = wm * 32 + mi * 16 + g;
            int cbase = n0 + wn * 32 + ni * 8 + 2 * tg;
#pragma unroll
            for (int q = 0; q < 4; q++) {
                int rr = m0 + rbase + (q >> 1) * 8;
                int c = cbase + (q & 1);
                if (rr < rows) {
                    float gv = accG[mi][ni][q], uv = accU[mi][ni][q];
                    float h = gv / (1.f + expf(-gv)) * uv;
                    g_h[(hbase + rr) * HID + c] = h;
                }
            }
        }
    }
}

// ---------------- kernel 5: FFN2 — out += coef * (h W2^T) --------------------
// grid: (DIM/BN=16, T/BM=64, 9 segments), block 256
__global__ __launch_bounds__(256) void ffn2_kernel(
    const float* __restrict__ w2, const float* __restrict__ sw2, float* __restrict__ out)
{
    extern __shared__ float smem[];
    const int z = blockIdx.z;
    const int rows = (z < NE) ? g_counts[z] : T_TOK;
    const int m0 = blockIdx.y * BM;
    if (m0 >= rows) return;
    const int segoff = (z < NE) ? g_offsets[z] : 0;
    const size_t hbase = (z < NE) ? (size_t)g_offsets[z] : (size_t)(T_TOK * TOPK);
    const float* W2 = (z < NE) ? (w2 + (size_t)z * DIM * HID) : sw2;
    const int n0 = blockIdx.x * BN;
    const int tid = threadIdx.x;

    auto loadA = [&](int it, int buf) {
        float* As = smem + buf * ST2;
        int kt = it * BK;
#pragma unroll
        for (int i = 0; i < 4; i++) {
            int j = tid + i * 256;
            int r = j >> 3, kq = j & 7;
            int rr = (m0 + r < rows) ? (m0 + r) : m0;
            const float* src = g_h + (hbase + rr) * HID + kt + kq * 4;
            cp16(smem_u32(&As[r * (BK + 4) + kq * 4]), src);
        }
    };
    auto loadB = [&](int it, int buf) {
        float* Bs = smem + buf * ST2 + SA;
        int kt = it * BK;
#pragma unroll
        for (int i = 0; i < 2; i++) {
            int j = tid + i * 256;
            int n = j >> 3, kq = j & 7;
            cp16(smem_u32(&Bs[n * (BK + 4) + kq * 4]),
                 W2 + (size_t)(n0 + n) * HID + kt + kq * 4);
        }
    };

    const int lane = tid & 31, warp = tid >> 5;
    const int wm = warp & 3, wn = warp >> 2;
    const int g = lane >> 2, tg = lane & 3;

    float acc[2][4][4];
#pragma unroll
    for (int a = 0; a < 2; a++)
#pragma unroll
        for (int b = 0; b < 4; b++)
#pragma unroll
            for (int c = 0; c < 4; c++) acc[a][b][c] = 0.f;

    const int NIT = HID / BK;  // 86
    loadA(0, 0); loadB(0, 0); cp_commit();
    for (int it = 0; it < NIT; ++it) {
        int buf = it & 1;
        if (it + 1 < NIT) { loadA(it + 1, buf ^ 1); loadB(it + 1, buf ^ 1); cp_commit(); cp_wait<1>(); }
        else               { cp_wait<0>(); }
        __syncthreads();
        float* As = smem + buf * ST2;
        float* Bs = As + SA;
#pragma unroll
        for (int kk = 0; kk < 4; kk++) {
            int kb = kk * 8;
            uint32_t af[2][4];
#pragma unroll
            for (int mi = 0; mi < 2; mi++) {
                int mb = wm * 32 + mi * 16;
                af[mi][0] = f2tf(As[(mb + g    ) * (BK + 4) + kb + tg    ]);
                af[mi][1] = f2tf(As[(mb + g + 8) * (BK + 4) + kb + tg    ]);
                af[mi][2] = f2tf(As[(mb + g    ) * (BK + 4) + kb + tg + 4]);
                af[mi][3] = f2tf(As[(mb + g + 8) * (BK + 4) + kb + tg + 4]);
            }
#pragma unroll
            for (int ni = 0; ni < 4; ni++) {
                int nb = wn * 32 + ni * 8;
                uint32_t bf[2];
                bf[0] = f2tf(Bs[(nb + g) * (BK + 4) + kb + tg    ]);
                bf[1] = f2tf(Bs[(nb + g) * (BK + 4) + kb + tg + 4]);
#pragma unroll
                for (int mi = 0; mi < 2; mi++) mma_tf32(acc[mi][ni], af[mi], bf);
            }
        }
        __syncthreads();
    }

    // epilogue: scatter-add with gate coefficient
#pragma unroll
    for (int mi = 0; mi < 2; mi++) {
#pragma unroll
        for (int rq = 0; rq < 2; rq++) {
            int rr = m0 + wm * 32 + mi * 16 + g + rq * 8;
            if (rr >= rows) continue;
            int   tok = (z < NE) ? g_perm[segoff + rr] : rr;
            float cf  = (z < NE) ? g_coef[segoff + rr] : 1.f;
            float* orow = out + (size_t)tok * DIM;
#pragma unroll
            for (int ni = 0; ni < 4; ni++) {
                int c = n0 + wn * 32 + ni * 8 + 2 * tg;
                atomicAdd(&orow[c],     cf * acc[mi][ni][rq * 2]);
                atomicAdd(&orow[c + 1], cf * acc[mi][ni][rq * 2 + 1]);
            }
        }
    }
}

// ---------------- launcher ----------------------------------------------------
extern "C" void kernel_launch(void* const* d_in, const int* in_sizes, int n_in,
                              void* d_out, int out_size) {
    const float* x   = (const float*)d_in[0];
    const float* gw  = (const float*)d_in[1];
    const float* w1  = (const float*)d_in[2];
    const float* w2  = (const float*)d_in[3];
    const float* w3  = (const float*)d_in[4];
    const float* sw1 = (const float*)d_in[5];
    const float* sw2 = (const float*)d_in[6];
    const float* sw3 = (const float*)d_in[7];
    float* out = (float*)d_out;

    // >48KB dynamic smem opt-in (idempotent, not a stream op)
    cudaFuncSetAttribute(ffn1_kernel, cudaFuncAttributeMaxDynamicSharedMemorySize, SMEM1);
    cudaFuncSetAttribute(ffn2_kernel, cudaFuncAttributeMaxDynamicSharedMemorySize, SMEM2);

    zero_kernel<<<2048, 256>>>(out);
    gate_kernel<<<T_TOK / 8, 256>>>(x, gw);
    scan_kernel<<<1, 32>>>();
    scatter_kernel<<<T_TOK / 256, 256>>>();

    dim3 g1(HID / BN, T_TOK / BM, NE + 1);
    ffn1_kernel<<<g1, 256, SMEM1>>>(x, w1, w3, sw1, sw3);
    dim3 g2(DIM / BN, T_TOK / BM, NE + 1);
    ffn2_kernel<<<g2, 256, SMEM2>>>(w2, sw2, out);
}